// round 8
// baseline (speedup 1.0000x reference)
#include <cuda_runtime.h>
#include <cstdint>

#define HDIM 4096
#define VOCAB 50257
#define SEQL 2048
#define TOPK 50
#define MINKEEP 5
#define HSPLIT 4
#define HCHUNK (HDIM / HSPLIT)          // 1024
#define NVBLK ((VOCAB + 255) / 256)     // 197
#define CAP 1024
#define BMW ((VOCAB + 31) / 32)

__device__ float g_x[HDIM];
__device__ float g_part[HSPLIT * VOCAB];
__device__ float g_logits[VOCAB];
__device__ unsigned int g_hist[65536];
__device__ unsigned int g_coarse[1024];
__device__ unsigned int g_bitmap[BMW];
__device__ unsigned int g_Bf;
__device__ int g_cnt;
__device__ unsigned int g_sync1;
__device__ unsigned int g_sync2;
__device__ unsigned int g_thr_ready;
__device__ float g_cv[CAP];
__device__ int   g_ci[CAP];

__device__ __forceinline__ unsigned int fkey(float f) {
    unsigned int u = __float_as_uint(f);
    return (u & 0x80000000u) ? ~u : (u | 0x80000000u);
}

// software grid barrier — valid because all NVBLK blocks are co-resident
__device__ __forceinline__ void grid_sync(unsigned int* ctr, unsigned int target) {
    __syncthreads();
    if (threadIdx.x == 0) {
        __threadfence();                       // release prior writes
        unsigned int prev = atomicAdd(ctr, 1u);
        if (prev + 1u < target) {
            while (atomicAdd(ctr, 0u) < target) __nanosleep(64);
        }
    }
    __syncthreads();
    __threadfence();                           // acquire
}

// ---------------- LayerNorm + penalty bitmap + per-replay resets (one block) ----------------
__global__ void ln_kernel(const float* __restrict__ hin,
                          const float* __restrict__ gamma,
                          const float* __restrict__ beta,
                          const void* __restrict__ ids_raw) {
    __shared__ float xs[HDIM];
    __shared__ float red[1024];
    __shared__ int bad;
    int tid = threadIdx.x;
    for (int i = tid; i < BMW; i += 1024) g_bitmap[i] = 0u;
    if (tid == 0) { bad = 0; g_cnt = 0; g_sync1 = 0u; g_sync2 = 0u; g_thr_ready = 0u; }

    float s = 0.f;
    for (int i = tid; i < HDIM; i += 1024) { float v = hin[i]; xs[i] = v; s += v; }
    red[tid] = s; __syncthreads();
    for (int o = 512; o > 0; o >>= 1) { if (tid < o) red[tid] += red[tid + o]; __syncthreads(); }
    float mu = red[0] / HDIM;
    __syncthreads();
    float sq = 0.f;
    for (int i = tid; i < HDIM; i += 1024) { float d = xs[i] - mu; sq += d * d; }
    red[tid] = sq; __syncthreads();
    for (int o = 512; o > 0; o >>= 1) { if (tid < o) red[tid] += red[tid + o]; __syncthreads(); }
    float rstd = rsqrtf(red[0] / HDIM + 1e-5f);
    for (int i = tid; i < HDIM; i += 1024)
        g_x[i] = (xs[i] - mu) * rstd * gamma[i] + beta[i];

    // ---- int64-vs-int32 detection (first 8KB valid under both) ----
    const long long* ll = (const long long*)ids_raw;
    long long probe = ll[tid];
    if (probe < 0 || probe >= VOCAB) atomicOr(&bad, 1);
    __syncthreads();
    int is64 = (bad == 0);
    long long id0, id1;
    if (is64) { id0 = ll[tid]; id1 = ll[tid + 1024]; }
    else {
        const int* ii = (const int*)ids_raw;
        id0 = ii[tid]; id1 = ii[tid + 1024];
    }
    atomicOr(&g_bitmap[(int)(id0 >> 5)], 1u << ((int)id0 & 31));
    atomicOr(&g_bitmap[(int)(id1 >> 5)], 1u << ((int)id1 & 31));
}

// ---------------- GEMV: 16 loads in flight per thread, single wave (UNCHANGED) ----------------
__global__ void __launch_bounds__(256, 6) gemv_kernel(const float* __restrict__ W) {
    __shared__ float xs[HCHUNK];
    int tid = threadIdx.x;
    int hb = blockIdx.y;
    int h0 = hb * HCHUNK;
    int gb = (hb * gridDim.x + blockIdx.x) * 256 + tid;
    if (gb < 65536) g_hist[gb] = 0u;
    if (gb < 1024)  g_coarse[gb] = 0u;
    for (int i = tid; i < HCHUNK; i += 256) xs[i] = g_x[h0 + i];
    __syncthreads();
    int v = blockIdx.x * 256 + tid;
    if (v >= VOCAB) return;
    const float* wp = W + (size_t)h0 * VOCAB + v;
    float a0 = 0.f, a1 = 0.f, a2 = 0.f, a3 = 0.f;
    for (int i = 0; i < HCHUNK; i += 16) {
        float w[16];
#pragma unroll
        for (int j = 0; j < 16; j++) w[j] = __ldcs(wp + (size_t)j * VOCAB);
        wp += 16 * (size_t)VOCAB;
#pragma unroll
        for (int j = 0; j < 16; j += 4) {
            a0 += xs[i + j]     * w[j];
            a1 += xs[i + j + 1] * w[j + 1];
            a2 += xs[i + j + 2] * w[j + 2];
            a3 += xs[i + j + 3] * w[j + 3];
        }
    }
    g_part[hb * VOCAB + v] = (a0 + a1) + (a2 + a3);
}

// ---- ONE tail kernel: fuse -> gridsync -> (block0 thresh || prefetch) -> collect
//      -> gridsync -> block0 sort+sample ----
__global__ void __launch_bounds__(256) tail_kernel(
        const float* __restrict__ pen,
        const float* __restrict__ tp_,
        const float* __restrict__ temp_,
        float* __restrict__ out, int out_size) {
    __shared__ unsigned cs[1024];
    __shared__ unsigned ws[32];
    __shared__ unsigned fb[64];
    __shared__ int sh_t;
    __shared__ unsigned sh_acc;
    __shared__ float cv[CAP];
    __shared__ int   ci[CAP];
    __shared__ float tv[TOPK];
    __shared__ int   tix[TOPK];
    __shared__ float sx[TOPK];
    __shared__ float sp[TOPK];

    int tid = threadIdx.x;
    int v = blockIdx.x * 256 + tid;

    // ---- phase 1: combine + penalty + two-level histogram ----
    if (v < VOCAB) {
        float s = (g_part[v] + g_part[VOCAB + v]) +
                  (g_part[2 * VOCAB + v] + g_part[3 * VOCAB + v]);
        if ((g_bitmap[v >> 5] >> (v & 31)) & 1u) {
            float p = pen[0];
            s = (s < 0.f) ? s * p : s / p;
        }
        g_logits[v] = s;
        unsigned k = fkey(s);
        atomicAdd(&g_hist[k >> 16], 1u);
        atomicAdd(&g_coarse[k >> 22], 1u);
    }
    grid_sync(&g_sync1, NVBLK);

    // ---- phase 2: prefetch own logit (final now); block 0 computes threshold ----
    float myf = (v < VOCAB) ? g_logits[v] : 0.f;
    unsigned myk = fkey(myf);

    if (blockIdx.x == 0) {
        for (int i = tid; i < 1024; i += 256) cs[i] = g_coarse[i];
        __syncthreads();
        if (tid < 32) {
            unsigned s = 0;
            for (int j = 0; j < 32; j++) s += cs[tid * 32 + j];
            ws[tid] = s;
        }
        __syncthreads();
        if (tid == 0) {
            unsigned acc = 0;
            int w = 31;
            for (; w > 0; --w) {
                if (acc + ws[w] >= (unsigned)TOPK) break;
                acc += ws[w];
            }
            int t = w * 32;
            for (int b = w * 32 + 31; b >= w * 32; --b) {
                unsigned cc = cs[b];
                if (acc + cc >= (unsigned)TOPK) { t = b; break; }
                acc += cc;
            }
            sh_t = t; sh_acc = acc;
        }
        __syncthreads();
        if (tid < 64) fb[tid] = g_hist[sh_t * 64 + tid];
        __syncthreads();
        if (tid == 0) {
            unsigned acc = sh_acc;
            int B = sh_t * 64;
            for (int b = 63; b >= 0; --b) {
                unsigned cc = fb[b];
                if (acc + cc >= (unsigned)TOPK) { B = sh_t * 64 + b; break; }
                acc += cc;
            }
            g_Bf = (unsigned)B << 16;
            __threadfence();
            atomicExch(&g_thr_ready, 1u);
        }
    }
    if (tid == 0) {
        while (atomicAdd(&g_thr_ready, 0u) == 0u) __nanosleep(32);
    }
    __syncthreads();
    __threadfence();
    unsigned Bf = g_Bf;

    // ---- collect ----
    if (v < VOCAB && myk >= Bf) {
        int p = atomicAdd(&g_cnt, 1);
        if (p < CAP) { g_cv[p] = myf; g_ci[p] = v; }
    }
    grid_sync(&g_sync2, NVBLK);

    // ---- phase 3: block 0 rank-sorts + samples ----
    if (blockIdx.x != 0) return;
    int n = min(g_cnt, CAP);
    for (int i = tid; i < n; i += 256) { cv[i] = g_cv[i]; ci[i] = g_ci[i]; }
    __syncthreads();
    for (int i = tid; i < n; i += 256) {
        float val = cv[i]; int ix = ci[i];
        int r = 0;
        for (int j = 0; j < n; j++) {
            float vj = cv[j];
            if (vj > val || (vj == val && ci[j] < ix)) r++;
        }
        if (r < TOPK) { tv[r] = val; tix[r] = ix; }
    }
    __syncthreads();
    if (tid < TOPK) sx[tid] = tv[tid] / temp_[0];
    __syncthreads();
    if (tid < TOPK) sp[tid] = expf(sx[tid] - sx[0]);
    __syncthreads();
    if (tid == 0) {
        float tp = tp_[0];
        float m = sx[0];
        float s = 0.f;
        for (int i = 0; i < TOPK; i++) s += sp[i];
        float cum = 0.f, s2 = 0.f;
        for (int i = 0; i < TOPK; i++) {
            cum += sp[i] / s;
            bool keep = (cum < tp) || (i < MINKEEP);
            float f = keep ? sx[i] : -1000.0f;
            float e = expf(f - m);
            sp[i] = e;
            s2 += e;
        }
        sx[0] = s2;
    }
    __syncthreads();
    if (tid < TOPK) out[tid] = sp[tid] / sx[0];
    if (out_size >= 2 * TOPK && tid < TOPK) out[TOPK + tid] = (float)tix[tid];
}

extern "C" void kernel_launch(void* const* d_in, const int* in_sizes, int n_in,
                              void* d_out, int out_size) {
    const float* hidden = (const float*)d_in[0];
    const void*  ids    = d_in[1];
    const float* top_p  = (const float*)d_in[2];
    const float* temp   = (const float*)d_in[3];
    const float* pen    = (const float*)d_in[4];
    const float* gamma  = (const float*)d_in[5];
    const float* beta   = (const float*)d_in[6];
    const float* W      = (const float*)d_in[7];
    float* out = (float*)d_out;

    ln_kernel<<<1, 1024>>>(hidden, gamma, beta, ids);
    dim3 g(NVBLK, HSPLIT);
    gemv_kernel<<<g, 256>>>(W);
    tail_kernel<<<NVBLK, 256>>>(pen, top_p, temp, out, out_size);
}

// round 9
// speedup vs baseline: 1.0323x; 1.0323x over previous
#include <cuda_runtime.h>
#include <cstdint>

#define HDIM 4096
#define VOCAB 50257
#define SEQL 2048
#define TOPK 50
#define MINKEEP 5
#define HSPLIT 4
#define HCHUNK (HDIM / HSPLIT)          // 1024
#define NVBLK ((VOCAB + 255) / 256)     // 197
#define CAP 2048
#define BMW ((VOCAB + 31) / 32)

__device__ float g_mu;
__device__ float g_rstd;
__device__ float g_part[HSPLIT * VOCAB];
__device__ float g_logits[VOCAB];
__device__ unsigned int g_hist[65536];
__device__ unsigned int g_coarse[1024];
__device__ unsigned int g_bitmap[BMW];
__device__ unsigned int g_Bf;
__device__ int g_cnt;
__device__ float g_cv[CAP];
__device__ int   g_ci[CAP];

__device__ __forceinline__ unsigned int fkey(float f) {
    unsigned int u = __float_as_uint(f);
    return (u & 0x80000000u) ? ~u : (u | 0x80000000u);
}

// ------- prep: LN statistics (scalars only) + penalty bitmap (one block, 1024 thr) -------
__global__ void __launch_bounds__(1024) prep_kernel(const float* __restrict__ hin,
                                                    const void* __restrict__ ids_raw) {
    __shared__ float ws[32];
    __shared__ float sh_mu;
    __shared__ int bad;
    int tid = threadIdx.x;
    int lane = tid & 31, warp = tid >> 5;

    for (int i = tid; i < BMW; i += 1024) g_bitmap[i] = 0u;
    if (tid == 0) bad = 0;

    // mean: one float4 per thread (4096 = 1024*4)
    float4 h = ((const float4*)hin)[tid];
    float s = (h.x + h.y) + (h.z + h.w);
#pragma unroll
    for (int o = 16; o > 0; o >>= 1) s += __shfl_down_sync(0xffffffffu, s, o);
    if (lane == 0) ws[warp] = s;
    __syncthreads();
    if (warp == 0) {
        float t = ws[lane];
#pragma unroll
        for (int o = 16; o > 0; o >>= 1) t += __shfl_down_sync(0xffffffffu, t, o);
        if (lane == 0) sh_mu = t / HDIM;
    }
    __syncthreads();
    float mu = sh_mu;

    // variance
    float dx = h.x - mu, dy = h.y - mu, dz = h.z - mu, dw = h.w - mu;
    float q = (dx * dx + dy * dy) + (dz * dz + dw * dw);
#pragma unroll
    for (int o = 16; o > 0; o >>= 1) q += __shfl_down_sync(0xffffffffu, q, o);
    if (lane == 0) ws[warp] = q;
    __syncthreads();
    if (warp == 0) {
        float t = ws[lane];
#pragma unroll
        for (int o = 16; o > 0; o >>= 1) t += __shfl_down_sync(0xffffffffu, t, o);
        if (lane == 0) { g_mu = mu; g_rstd = rsqrtf(t / HDIM + 1e-5f); }
    }

    // ---- int64-vs-int32 detection (first 8KB valid under both) ----
    const long long* ll = (const long long*)ids_raw;
    long long probe = ll[tid];
    if (probe < 0 || probe >= VOCAB) atomicOr(&bad, 1);
    __syncthreads();
    int is64 = (bad == 0);
    long long id0, id1;
    if (is64) { id0 = ll[tid]; id1 = ll[tid + 1024]; }
    else {
        const int* ii = (const int*)ids_raw;
        id0 = ii[tid]; id1 = ii[tid + 1024];
    }
    atomicOr(&g_bitmap[(int)(id0 >> 5)], 1u << ((int)id0 & 31));
    atomicOr(&g_bitmap[(int)(id1 >> 5)], 1u << ((int)id1 & 31));
}

// ------- GEMV: LN applied inline while staging xs; 16 loads in flight (core UNCHANGED) -------
__global__ void __launch_bounds__(256, 6) gemv_kernel(const float* __restrict__ W,
                                                      const float* __restrict__ hin,
                                                      const float* __restrict__ gamma,
                                                      const float* __restrict__ beta) {
    __shared__ float xs[HCHUNK];
    int tid = threadIdx.x;
    int hb = blockIdx.y;
    int h0 = hb * HCHUNK;
    int gb = (hb * gridDim.x + blockIdx.x) * 256 + tid;
    if (gb < 65536) g_hist[gb] = 0u;
    if (gb < 1024)  g_coarse[gb] = 0u;
    float mu = g_mu, rstd = g_rstd;
    for (int i = tid; i < HCHUNK; i += 256)
        xs[i] = (hin[h0 + i] - mu) * rstd * gamma[h0 + i] + beta[h0 + i];
    __syncthreads();
    int v = blockIdx.x * 256 + tid;
    if (v >= VOCAB) return;
    const float* wp = W + (size_t)h0 * VOCAB + v;
    float a0 = 0.f, a1 = 0.f, a2 = 0.f, a3 = 0.f;
    for (int i = 0; i < HCHUNK; i += 16) {
        float w[16];
#pragma unroll
        for (int j = 0; j < 16; j++) w[j] = __ldcs(wp + (size_t)j * VOCAB);
        wp += 16 * (size_t)VOCAB;
#pragma unroll
        for (int j = 0; j < 16; j += 4) {
            a0 += xs[i + j]     * w[j];
            a1 += xs[i + j + 1] * w[j + 1];
            a2 += xs[i + j + 2] * w[j + 2];
            a3 += xs[i + j + 3] * w[j + 3];
        }
    }
    g_part[hb * VOCAB + v] = (a0 + a1) + (a2 + a3);
}

// ---------------- combine + penalty + two-level histogram (UNCHANGED from R5) ----------------
__global__ void fuse_kernel(const float* __restrict__ pen) {
    int v = blockIdx.x * 256 + threadIdx.x;
    if (v >= VOCAB) return;
    float s = (g_part[v] + g_part[VOCAB + v]) +
              (g_part[2 * VOCAB + v] + g_part[3 * VOCAB + v]);
    if ((g_bitmap[v >> 5] >> (v & 31)) & 1u) {
        float p = pen[0];
        s = (s < 0.f) ? s * p : s / p;
    }
    g_logits[v] = s;
    unsigned k = fkey(s);
    atomicAdd(&g_hist[k >> 16], 1u);
    atomicAdd(&g_coarse[k >> 22], 1u);
}

// ---------------- threshold: coarse scan + one 64-bin fine chunk (UNCHANGED from R5) ----------------
__global__ void thresh_kernel() {
    __shared__ unsigned cs[1024];
    __shared__ unsigned ws[32];
    __shared__ unsigned fb[64];
    __shared__ int sh_t;
    __shared__ unsigned sh_acc;
    int tid = threadIdx.x;
    unsigned c = g_coarse[tid];
    cs[tid] = c;
    unsigned s = c;
    for (int o = 16; o > 0; o >>= 1) s += __shfl_down_sync(0xffffffffu, s, o);
    if ((tid & 31) == 0) ws[tid >> 5] = s;
    __syncthreads();
    if (tid == 0) {
        unsigned acc = 0;
        int w = 31;
        for (; w > 0; --w) {
            if (acc + ws[w] >= (unsigned)TOPK) break;
            acc += ws[w];
        }
        int t = w * 32;
        for (int b = w * 32 + 31; b >= w * 32; --b) {
            unsigned cc = cs[b];
            if (acc + cc >= (unsigned)TOPK) { t = b; break; }
            acc += cc;
        }
        sh_t = t; sh_acc = acc;
    }
    __syncthreads();
    int t = sh_t;
    if (tid < 64) fb[tid] = g_hist[t * 64 + tid];
    __syncthreads();
    if (tid == 0) {
        unsigned acc = sh_acc;
        int B = t * 64;
        for (int b = 63; b >= 0; --b) {
            unsigned cc = fb[b];
            if (acc + cc >= (unsigned)TOPK) { B = t * 64 + b; break; }
            acc += cc;
        }
        g_Bf = (unsigned)B << 16;
        g_cnt = 0;
    }
}

// ---------------- parallel candidate collection (UNCHANGED from R5) ----------------
__global__ void collect_kernel() {
    int v = blockIdx.x * 256 + threadIdx.x;
    if (v >= VOCAB) return;
    float f = g_logits[v];
    if (fkey(f) >= g_Bf) {
        int p = atomicAdd(&g_cnt, 1);
        if (p < CAP) { g_cv[p] = f; g_ci[p] = v; }
    }
}

// ---------------- rank-sort + sampling (UNCHANGED from R5) ----------------
__global__ void __launch_bounds__(1024) sort_sample_kernel(
        const float* __restrict__ tp_,
        const float* __restrict__ temp_,
        float* __restrict__ out, int out_size) {
    __shared__ float cv[CAP];
    __shared__ int   ci[CAP];
    __shared__ float tv[TOPK];
    __shared__ int   tix[TOPK];
    __shared__ float sx[TOPK];
    __shared__ float sp[TOPK];
    int tid = threadIdx.x;
    int n = min(g_cnt, CAP);
    for (int i = tid; i < n; i += 1024) { cv[i] = g_cv[i]; ci[i] = g_ci[i]; }
    __syncthreads();
    for (int i = tid; i < n; i += 1024) {
        float v = cv[i]; int ix = ci[i];
        int r = 0;
        for (int j = 0; j < n; j++) {
            float vj = cv[j];
            if (vj > v || (vj == v && ci[j] < ix)) r++;
        }
        if (r < TOPK) { tv[r] = v; tix[r] = ix; }
    }
    __syncthreads();
    if (tid < TOPK) sx[tid] = tv[tid] / temp_[0];
    __syncthreads();
    if (tid < TOPK) sp[tid] = expf(sx[tid] - sx[0]);
    __syncthreads();
    if (tid == 0) {
        float tp = tp_[0];
        float m = sx[0];
        float s = 0.f;
        for (int i = 0; i < TOPK; i++) s += sp[i];
        float cum = 0.f, s2 = 0.f;
        for (int i = 0; i < TOPK; i++) {
            cum += sp[i] / s;
            bool keep = (cum < tp) || (i < MINKEEP);
            float f = keep ? sx[i] : -1000.0f;
            float e = expf(f - m);
            sp[i] = e;
            s2 += e;
        }
        sx[0] = s2;
    }
    __syncthreads();
    if (tid < TOPK) out[tid] = sp[tid] / sx[0];
    if (out_size >= 2 * TOPK && tid < TOPK) out[TOPK + tid] = (float)tix[tid];
}

extern "C" void kernel_launch(void* const* d_in, const int* in_sizes, int n_in,
                              void* d_out, int out_size) {
    const float* hidden = (const float*)d_in[0];
    const void*  ids    = d_in[1];
    const float* top_p  = (const float*)d_in[2];
    const float* temp   = (const float*)d_in[3];
    const float* pen    = (const float*)d_in[4];
    const float* gamma  = (const float*)d_in[5];
    const float* beta   = (const float*)d_in[6];
    const float* W      = (const float*)d_in[7];
    float* out = (float*)d_out;

    prep_kernel<<<1, 1024>>>(hidden, ids);
    dim3 g(NVBLK, HSPLIT);
    gemv_kernel<<<g, 256>>>(W, hidden, gamma, beta);
    fuse_kernel<<<NVBLK, 256>>>(pen);
    thresh_kernel<<<1, 1024>>>();
    collect_kernel<<<NVBLK, 256>>>();
    sort_sample_kernel<<<1, 1024>>>(top_p, temp, out, out_size);
}